// round 5
// baseline (speedup 1.0000x reference)
#include <cuda_runtime.h>
#include <stdint.h>
#include <math.h>

// Problem constants
#define BB 8
#define NN 2048
#define DD 1024

// Scratch (static device globals -- runtime allocation is forbidden).
// Zero-initialized at load; skipped (masked) Q/K rows stay 0 => finite logits
// in never-read regions.
__device__ float g_Q[BB * NN * DD];
__device__ float g_K[BB * NN * DD];
__device__ float g_V[BB * NN * DD];
__device__ float g_Y[BB * NN * DD];
__device__ float g_X[BB * NN * DD];    // tf32-rounded copy of x
__device__ float g_Wq[DD * DD];        // tf32-rounded weights
__device__ float g_Wk[DD * DD];
__device__ float g_Wv[DD * DD];
__device__ float g_Wo[DD * DD];
__device__ int   g_len[BB];

__device__ __forceinline__ uint32_t f2tf(float f)
{
    uint32_t r;
    asm("cvt.rna.tf32.f32 %0, %1;" : "=r"(r) : "f"(f));
    return r;
}

// ---------------------------------------------------------------------------
// Mask length probe (prefix mask, element [0,1] is always true)
// ---------------------------------------------------------------------------
__global__ void mask_len_kernel(const unsigned char* __restrict__ m)
{
    const int b = blockIdx.x, tid = threadIdx.x;
    int mode;
    if (m[1] != 0) {
        mode = 0;
    } else {
        uint32_t w0 = *(const uint32_t*)m;
        mode = (w0 == 0x3f800000u) ? 2 : 1;
    }
    int cnt = 0;
    for (int i = tid; i < NN; i += 256) {
        size_t idx = (size_t)b * NN + i;
        bool t;
        if (mode == 0)      t = m[idx] != 0;
        else if (mode == 1) t = ((const int*)m)[idx] != 0;
        else                t = ((const float*)m)[idx] != 0.0f;
        cnt += t ? 1 : 0;
    }
    #pragma unroll
    for (int o = 16; o > 0; o >>= 1) cnt += __shfl_xor_sync(0xffffffffu, cnt, o);
    __shared__ int sc[8];
    if ((tid & 31) == 0) sc[tid >> 5] = cnt;
    __syncthreads();
    if (tid == 0) {
        int t = 0;
        #pragma unroll
        for (int w = 0; w < 8; w++) t += sc[w];
        g_len[b] = t;
    }
}

// ---------------------------------------------------------------------------
// Elementwise tf32 rounding (fp32 -> fp32 with low mantissa bits zeroed, RNA)
// ---------------------------------------------------------------------------
__global__ void __launch_bounds__(256) cvt_tf32_kernel(
    const float* __restrict__ in, float* __restrict__ out, int n4)
{
    int i = blockIdx.x * 256 + threadIdx.x;
    if (i < n4) {
        float4 v = ((const float4*)in)[i];
        v.x = __uint_as_float(f2tf(v.x));
        v.y = __uint_as_float(f2tf(v.y));
        v.z = __uint_as_float(f2tf(v.z));
        v.w = __uint_as_float(f2tf(v.w));
        ((float4*)out)[i] = v;
    }
}

// ---------------------------------------------------------------------------
// tf32 tiled GEMM, CTA tile 128x128x16, 4-stage cp.async pipeline.
// 8 warps (2 M x 4 N), warp tile 64x32, mma.m16n8k8.tf32.
//
//   A_KM=false: A gmem (m,k) k-contiguous  -> smem As[m][20]
//   A_KM=true : A gmem (k,m) m-contiguous  -> smem As[k][136]
//   B_KN likewise for B.
//   CVT_A: apply cvt.rna.tf32 to A fragments (only for A = att, which must
//          remain full fp32 in memory). Other operands are pre-rounded.
//   ROUND_OUT: round C to tf32 in the epilogue (scratch consumed by later
//              GEMMs) -- bit-identical to converting at the consumer.
//
// skip_mode: 0 none
//            1 skip CTA if its M-tile rows are all masked (projections)
//            2 skip CTA if M-tile or N-tile fully masked (logits)
//            3 (A^T V) m0 >= len: rows i>=len only -- contributions from
//              k=j<len are EXACT zeros (att[b,j<len,i>=len] == +0), so start
//              at k_lo = len&~15 (bit-identical). m0 < len: FULL K (uniform
//              rows j>=len contribute 1/N to every i -- must not truncate).
// ---------------------------------------------------------------------------
#define BM 128
#define BN 128
#define BK 16
#define LDK 20
#define LDT 136
#define SSZ 2560
#define NSTAGE 4
#define SMEM_BYTES (NSTAGE * SSZ * 2 * 4)

__device__ __forceinline__ void cpasync16(uint32_t dst, const float* src)
{
    asm volatile("cp.async.cg.shared.global [%0], [%1], 16;" :: "r"(dst), "l"(src));
}

template <bool A_KM, bool B_KN, bool CVT_A, bool ROUND_OUT>
__global__ void __launch_bounds__(256, 2)
gemm_tf32(const float* __restrict__ A, const float* __restrict__ B,
          float* __restrict__ C,
          int lda, int ldb, int ldc, int K,
          long long sA, long long sB, long long sC, float alpha,
          int skip_mode)
{
    extern __shared__ __align__(16) float sm[];
    float* As = sm;
    float* Bs = sm + NSTAGE * SSZ;

    const int m0 = blockIdx.y * BM;
    const int n0 = blockIdx.x * BN;

    int k_lo = 0, k_hi = K;
    if (skip_mode == 1) {
        if ((m0 % NN) >= g_len[m0 / NN]) return;
    } else if (skip_mode == 2) {
        const int len = g_len[blockIdx.z];
        if (m0 >= len || n0 >= len) return;
    } else if (skip_mode == 3) {
        const int len = g_len[blockIdx.z];
        // Only all-masked row tiles may truncate (exact-zero prefix).
        // Such tiles exist only when len <= NN-BM, so >= (NN-len)/BK >= 8
        // iterations remain (3-stage prologue safe).
        if (m0 >= len) k_lo = len & ~(BK - 1);
    }

    const int tid = threadIdx.x;
    const float* Ab = A + (long long)blockIdx.z * sA;
    const float* Bb = B + (long long)blockIdx.z * sB;
    float* Cb = C + (long long)blockIdx.z * sC;

    const int warp = tid >> 5, lane = tid & 31;
    const int wm = warp >> 2, wn = warp & 3;
    const int gr = lane >> 2, gc = lane & 3;

    const uint32_t sA0 = (uint32_t)__cvta_generic_to_shared(As);
    const uint32_t sB0 = (uint32_t)__cvta_generic_to_shared(Bs);

    float acc[4][4][4];
    #pragma unroll
    for (int mf = 0; mf < 4; mf++)
        #pragma unroll
        for (int nf = 0; nf < 4; nf++)
            #pragma unroll
            for (int r = 0; r < 4; r++) acc[mf][nf][r] = 0.0f;

    auto stage = [&](int buf, int k0) {
        #pragma unroll
        for (int it = 0; it < 2; ++it) {
            int c = tid + it * 256;
            if (!A_KM) {
                int row = c >> 2, koff = (c & 3) * 4;
                cpasync16(sA0 + (uint32_t)(buf * SSZ + row * LDK + koff) * 4u,
                          Ab + (long long)(m0 + row) * lda + k0 + koff);
            } else {
                int row = c >> 5, toff = (c & 31) * 4;
                cpasync16(sA0 + (uint32_t)(buf * SSZ + row * LDT + toff) * 4u,
                          Ab + (long long)(k0 + row) * lda + m0 + toff);
            }
        }
        #pragma unroll
        for (int it = 0; it < 2; ++it) {
            int c = tid + it * 256;
            if (!B_KN) {
                int row = c >> 2, koff = (c & 3) * 4;
                cpasync16(sB0 + (uint32_t)(buf * SSZ + row * LDK + koff) * 4u,
                          Bb + (long long)(n0 + row) * ldb + k0 + koff);
            } else {
                int row = c >> 5, toff = (c & 31) * 4;
                cpasync16(sB0 + (uint32_t)(buf * SSZ + row * LDT + toff) * 4u,
                          Bb + (long long)(k0 + row) * ldb + n0 + toff);
            }
        }
        asm volatile("cp.async.commit_group;");
    };

    auto lda_frag = [&](const float* p) -> uint32_t {
        return CVT_A ? f2tf(*p) : __float_as_uint(*p);
    };

    auto compute = [&](int buf) {
        const float* sa = &As[buf * SSZ];
        const float* sb = &Bs[buf * SSZ];
        #pragma unroll
        for (int kk = 0; kk < BK; kk += 8) {
            uint32_t a[4][4];
            #pragma unroll
            for (int mf = 0; mf < 4; mf++) {
                int mr = wm * 64 + mf * 16 + gr;
                if (!A_KM) {
                    a[mf][0] = lda_frag(&sa[(mr    ) * LDK + kk + gc    ]);
                    a[mf][1] = lda_frag(&sa[(mr + 8) * LDK + kk + gc    ]);
                    a[mf][2] = lda_frag(&sa[(mr    ) * LDK + kk + gc + 4]);
                    a[mf][3] = lda_frag(&sa[(mr + 8) * LDK + kk + gc + 4]);
                } else {
                    a[mf][0] = lda_frag(&sa[(kk + gc    ) * LDT + mr    ]);
                    a[mf][1] = lda_frag(&sa[(kk + gc    ) * LDT + mr + 8]);
                    a[mf][2] = lda_frag(&sa[(kk + gc + 4) * LDT + mr    ]);
                    a[mf][3] = lda_frag(&sa[(kk + gc + 4) * LDT + mr + 8]);
                }
            }
            uint32_t b[4][2];
            #pragma unroll
            for (int nf = 0; nf < 4; nf++) {
                int nc = wn * 32 + nf * 8 + gr;
                if (!B_KN) {
                    b[nf][0] = __float_as_uint(sb[nc * LDK + kk + gc    ]);
                    b[nf][1] = __float_as_uint(sb[nc * LDK + kk + gc + 4]);
                } else {
                    b[nf][0] = __float_as_uint(sb[(kk + gc    ) * LDT + nc]);
                    b[nf][1] = __float_as_uint(sb[(kk + gc + 4) * LDT + nc]);
                }
            }
            #pragma unroll
            for (int mf = 0; mf < 4; mf++)
                #pragma unroll
                for (int nf = 0; nf < 4; nf++) {
                    asm volatile(
                        "mma.sync.aligned.m16n8k8.row.col.f32.tf32.tf32.f32 "
                        "{%0,%1,%2,%3},{%4,%5,%6,%7},{%8,%9},{%0,%1,%2,%3};"
                        : "+f"(acc[mf][nf][0]), "+f"(acc[mf][nf][1]),
                          "+f"(acc[mf][nf][2]), "+f"(acc[mf][nf][3])
                        : "r"(a[mf][0]), "r"(a[mf][1]), "r"(a[mf][2]), "r"(a[mf][3]),
                          "r"(b[nf][0]), "r"(b[nf][1]));
                }
        }
    };

    // ---- prologue: fill 3 of 4 stages (>= 8 iterations in all used modes) ----
    stage(0, k_lo);
    stage(1, k_lo + BK);
    stage(2, k_lo + 2 * BK);
    asm volatile("cp.async.wait_group 2;");
    __syncthreads();

    int buf = 0;
    for (int k0 = k_lo; k0 < k_hi; k0 += BK) {
        if (k0 + 3 * BK < k_hi) stage((buf + 3) & 3, k0 + 3 * BK);
        else                    asm volatile("cp.async.commit_group;");  // uniform FIFO
        compute(buf);
        asm volatile("cp.async.wait_group 2;");
        __syncthreads();
        buf = (buf + 1) & 3;
    }

    // ---- epilogue ----
    #pragma unroll
    for (int mf = 0; mf < 4; mf++) {
        #pragma unroll
        for (int nf = 0; nf < 4; nf++) {
            int row = m0 + wm * 64 + mf * 16 + gr;
            int col = n0 + wn * 32 + nf * 8 + gc * 2;
            float o0 = acc[mf][nf][0] * alpha, o1 = acc[mf][nf][1] * alpha;
            float o2 = acc[mf][nf][2] * alpha, o3 = acc[mf][nf][3] * alpha;
            if (ROUND_OUT) {
                o0 = __uint_as_float(f2tf(o0));
                o1 = __uint_as_float(f2tf(o1));
                o2 = __uint_as_float(f2tf(o2));
                o3 = __uint_as_float(f2tf(o3));
            }
            *(float2*)&Cb[(long long)row * ldc + col]       = make_float2(o0, o1);
            *(float2*)&Cb[(long long)(row + 8) * ldc + col] = make_float2(o2, o3);
        }
    }
}

// ---------------------------------------------------------------------------
// Masked softmax over the last axis, in place on att [B, N, N].
// Overwrites EVERY element; masked entries become exact 0 / uniform rows.
// ---------------------------------------------------------------------------
__global__ void __launch_bounds__(256) softmax_kernel(float* __restrict__ att)
{
    const int b = blockIdx.y, i = blockIdx.x, tid = threadIdx.x;
    const int len = g_len[b];
    float* row = att + ((size_t)b * NN + i) * NN;

    if (i >= len) {
        const float u = 1.0f / (float)NN;
        for (int j = tid; j < NN; j += 256) row[j] = u;
        return;
    }

    float v[8];
    float mx = -3.4e38f;
    #pragma unroll
    for (int s = 0; s < 8; s++) {
        int j = tid + s * 256;
        v[s] = (j < len) ? row[j] : -3.4e38f;
        mx = fmaxf(mx, v[s]);
    }
    #pragma unroll
    for (int o = 16; o > 0; o >>= 1) mx = fmaxf(mx, __shfl_xor_sync(0xffffffffu, mx, o));
    __shared__ float sred[8];
    if ((tid & 31) == 0) sred[tid >> 5] = mx;
    __syncthreads();
    float M = sred[0];
    #pragma unroll
    for (int w = 1; w < 8; w++) M = fmaxf(M, sred[w]);

    float sum = 0.0f;
    #pragma unroll
    for (int s = 0; s < 8; s++) {
        int j = tid + s * 256;
        v[s] = (j < len) ? expf(v[s] - M) : 0.0f;
        sum += v[s];
    }
    #pragma unroll
    for (int o = 16; o > 0; o >>= 1) sum += __shfl_xor_sync(0xffffffffu, sum, o);
    __syncthreads();
    if ((tid & 31) == 0) sred[tid >> 5] = sum;
    __syncthreads();
    float S = 0.0f;
    #pragma unroll
    for (int w = 0; w < 8; w++) S += sred[w];
    const float inv = 1.0f / S;

    #pragma unroll
    for (int s = 0; s < 8; s++) {
        int j = tid + s * 256;
        row[j] = v[s] * inv;
    }
}

// ---------------------------------------------------------------------------
// Launch. Output layout: y [B,N,D] followed by att_weights [B,N,N].
// ---------------------------------------------------------------------------
extern "C" void kernel_launch(void* const* d_in, const int* in_sizes, int n_in,
                              void* d_out, int out_size)
{
    const float* x  = (const float*)d_in[0];
    const unsigned char* mask = (const unsigned char*)d_in[1];
    const float* Wq = (const float*)d_in[2];
    const float* Wk = (const float*)d_in[3];
    const float* Wv = (const float*)d_in[4];
    const float* Wo = (const float*)d_in[5];

    float* y_out = (float*)d_out;
    float* att   = (float*)d_out + (size_t)BB * NN * DD;

    void *pQ, *pK, *pV, *pY, *pX, *pWq, *pWk, *pWv, *pWo;
    cudaGetSymbolAddress(&pQ, g_Q);
    cudaGetSymbolAddress(&pK, g_K);
    cudaGetSymbolAddress(&pV, g_V);
    cudaGetSymbolAddress(&pY, g_Y);
    cudaGetSymbolAddress(&pX, g_X);
    cudaGetSymbolAddress(&pWq, g_Wq);
    cudaGetSymbolAddress(&pWk, g_Wk);
    cudaGetSymbolAddress(&pWv, g_Wv);
    cudaGetSymbolAddress(&pWo, g_Wo);
    float* Q = (float*)pQ;  float* Km = (float*)pK;
    float* V = (float*)pV;  float* Y  = (float*)pY;
    float* Xt = (float*)pX;
    float* Wqt = (float*)pWq; float* Wkt = (float*)pWk;
    float* Wvt = (float*)pWv; float* Wot = (float*)pWo;

    cudaFuncSetAttribute((const void*)gemm_tf32<false, false, false, true>,
                         cudaFuncAttributeMaxDynamicSharedMemorySize, SMEM_BYTES);
    cudaFuncSetAttribute((const void*)gemm_tf32<false, false, false, false>,
                         cudaFuncAttributeMaxDynamicSharedMemorySize, SMEM_BYTES);
    cudaFuncSetAttribute((const void*)gemm_tf32<true, true, true, true>,
                         cudaFuncAttributeMaxDynamicSharedMemorySize, SMEM_BYTES);

    const dim3 blk(256);

    // 0) mask lengths + input pre-rounding (independent kernels)
    mask_len_kernel<<<BB, 256>>>(mask);
    cvt_tf32_kernel<<<(BB * NN * DD / 4 + 255) / 256, 256>>>(x,  Xt,  BB * NN * DD / 4);
    cvt_tf32_kernel<<<(DD * DD / 4 + 255) / 256, 256>>>(Wq, Wqt, DD * DD / 4);
    cvt_tf32_kernel<<<(DD * DD / 4 + 255) / 256, 256>>>(Wk, Wkt, DD * DD / 4);
    cvt_tf32_kernel<<<(DD * DD / 4 + 255) / 256, 256>>>(Wv, Wvt, DD * DD / 4);
    cvt_tf32_kernel<<<(DD * DD / 4 + 255) / 256, 256>>>(Wo, Wot, DD * DD / 4);

    // 1) QKV projections (Q,K skip masked row-tiles; V full); outputs rounded
    {
        dim3 grid(DD / BN, (BB * NN) / BM, 1);
        gemm_tf32<false, false, false, true><<<grid, blk, SMEM_BYTES>>>(
            Xt, Wqt, Q,  DD, DD, DD, DD, 0, 0, 0, 0.06f, 1);
        gemm_tf32<false, false, false, true><<<grid, blk, SMEM_BYTES>>>(
            Xt, Wkt, Km, DD, DD, DD, DD, 0, 0, 0, 1.0f, 1);
        gemm_tf32<false, false, false, true><<<grid, blk, SMEM_BYTES>>>(
            Xt, Wvt, V,  DD, DD, DD, DD, 0, 0, 0, 1.0f, 0);
    }

    // 2) logits = Q @ K^T per batch (skip fully-masked tiles); att stays fp32
    {
        dim3 grid(NN / BN, NN / BM, BB);
        gemm_tf32<false, false, false, false><<<grid, blk, SMEM_BYTES>>>(
            Q, Km, att, DD, DD, NN, DD,
            (long long)NN * DD, (long long)NN * DD, (long long)NN * NN, 1.0f, 2);
    }

    // 3) masked softmax (in place; finalizes att_weights output)
    {
        dim3 grid(NN, BB);
        softmax_kernel<<<grid, blk>>>(att);
    }

    // 4) y = A^T @ V per batch; k_lo truncation ONLY for fully-masked row
    //    tiles (exact-zero prefix); Y rounded
    {
        dim3 grid(DD / BN, NN / BM, BB);
        gemm_tf32<true, true, true, true><<<grid, blk, SMEM_BYTES>>>(
            att, V, Y, NN, DD, DD, NN,
            (long long)NN * NN, (long long)NN * DD, (long long)NN * DD, 1.0f, 3);
    }

    // 5) output projection: out = Y @ Wo^T (full, fp32 out)
    {
        dim3 grid(DD / BN, (BB * NN) / BM, 1);
        gemm_tf32<false, false, false, false><<<grid, blk, SMEM_BYTES>>>(
            Y, Wot, y_out, DD, DD, DD, DD, 0, 0, 0, 1.0f, 0);
    }
}

// round 7
// speedup vs baseline: 1.0571x; 1.0571x over previous
#include <cuda_runtime.h>
#include <stdint.h>
#include <math.h>

// Problem constants
#define BB 8
#define NN 2048
#define DD 1024

// Scratch (static device globals -- runtime allocation is forbidden).
// Zero-initialized at load; skipped (masked) rows stay 0 forever.
__device__ float g_Q[BB * NN * DD];
__device__ float g_K[BB * NN * DD];
__device__ float g_V[BB * NN * DD];
__device__ float g_Y[BB * NN * DD];
__device__ float g_X[BB * NN * DD];    // tf32-rounded copy of x
__device__ float g_Wq[DD * DD];        // tf32-rounded weights
__device__ float g_Wk[DD * DD];
__device__ float g_Wv[DD * DD];
__device__ float g_Wo[DD * DD];
__device__ float g_SX[BB * DD];        // sum of masked x rows
__device__ float g_S [BB * DD];        // S = sum_{j>=len} V[j]  (fp32, via x)
__device__ float g_YS[BB * DD];        // yS = round(S/N) @ Wo^T
__device__ int   g_len[BB];

__device__ __forceinline__ uint32_t f2tf(float f)
{
    uint32_t r;
    asm("cvt.rna.tf32.f32 %0, %1;" : "=r"(r) : "f"(f));
    return r;
}

// ---------------------------------------------------------------------------
// Mask length probe (prefix mask, element [0,1] is always true)
// ---------------------------------------------------------------------------
__global__ void mask_len_kernel(const unsigned char* __restrict__ m)
{
    const int b = blockIdx.x, tid = threadIdx.x;
    int mode;
    if (m[1] != 0) {
        mode = 0;
    } else {
        uint32_t w0 = *(const uint32_t*)m;
        mode = (w0 == 0x3f800000u) ? 2 : 1;
    }
    int cnt = 0;
    for (int i = tid; i < NN; i += 256) {
        size_t idx = (size_t)b * NN + i;
        bool t;
        if (mode == 0)      t = m[idx] != 0;
        else if (mode == 1) t = ((const int*)m)[idx] != 0;
        else                t = ((const float*)m)[idx] != 0.0f;
        cnt += t ? 1 : 0;
    }
    #pragma unroll
    for (int o = 16; o > 0; o >>= 1) cnt += __shfl_xor_sync(0xffffffffu, cnt, o);
    __shared__ int sc[8];
    if ((tid & 31) == 0) sc[tid >> 5] = cnt;
    __syncthreads();
    if (tid == 0) {
        int t = 0;
        #pragma unroll
        for (int w = 0; w < 8; w++) t += sc[w];
        g_len[b] = t;
    }
}

// ---------------------------------------------------------------------------
// Elementwise tf32 rounding
// ---------------------------------------------------------------------------
__global__ void __launch_bounds__(256) cvt_tf32_kernel(
    const float* __restrict__ in, float* __restrict__ out, int n4)
{
    int i = blockIdx.x * 256 + threadIdx.x;
    if (i < n4) {
        float4 v = ((const float4*)in)[i];
        v.x = __uint_as_float(f2tf(v.x));
        v.y = __uint_as_float(f2tf(v.y));
        v.z = __uint_as_float(f2tf(v.z));
        v.w = __uint_as_float(f2tf(v.w));
        ((float4*)out)[i] = v;
    }
}

// ---------------------------------------------------------------------------
// sx[b,d] = sum_{j>=len} x[b,j,d]   (fp32, raw x)   grid(DD/256, BB)
// ---------------------------------------------------------------------------
__global__ void __launch_bounds__(256) sumx_kernel(const float* __restrict__ x)
{
    const int b = blockIdx.y;
    const int d = blockIdx.x * 256 + threadIdx.x;
    const int len = g_len[b];
    float s = 0.0f;
    for (int j = len; j < NN; ++j)
        s += x[((size_t)b * NN + j) * DD + d];
    g_SX[b * DD + d] = s;
}

// ---------------------------------------------------------------------------
// S[b,e] = sum_d sx[b,d] * Wv[e,d]  (fp32, raw Wv)   grid(DD/8, BB), blk 256
// ---------------------------------------------------------------------------
__global__ void __launch_bounds__(256) matvecS_kernel(const float* __restrict__ Wv)
{
    const int b = blockIdx.y;
    const int wid = threadIdx.x >> 5, lane = threadIdx.x & 31;
    const int e = blockIdx.x * 8 + wid;
    const float* sx = &g_SX[b * DD];
    const float* w = &Wv[(size_t)e * DD];
    float acc = 0.0f;
    for (int d = lane; d < DD; d += 32) acc += sx[d] * w[d];
    #pragma unroll
    for (int o = 16; o > 0; o >>= 1) acc += __shfl_xor_sync(0xffffffffu, acc, o);
    if (lane == 0) g_S[b * DD + e] = acc;
}

// ---------------------------------------------------------------------------
// yS[b,e] = sum_d round_tf32(S[b,d]/N) * Wot[e,d]   grid(DD/8, BB), blk 256
// (Wot = tf32-rounded Wo, matching the GEMM operand)
// ---------------------------------------------------------------------------
__global__ void __launch_bounds__(256) matvecYS_kernel(const float* __restrict__ Wot)
{
    const int b = blockIdx.y;
    const int wid = threadIdx.x >> 5, lane = threadIdx.x & 31;
    const int e = blockIdx.x * 8 + wid;
    const float invN = 1.0f / (float)NN;
    const float* S = &g_S[b * DD];
    const float* w = &Wot[(size_t)e * DD];
    float acc = 0.0f;
    for (int d = lane; d < DD; d += 32)
        acc += __uint_as_float(f2tf(S[d] * invN)) * w[d];
    #pragma unroll
    for (int o = 16; o > 0; o >>= 1) acc += __shfl_xor_sync(0xffffffffu, acc, o);
    if (lane == 0) g_YS[b * DD + e] = acc;
}

// ---------------------------------------------------------------------------
// Y finalize: i<len: Y = round_tf32(Yraw + S/N); i>=len: Y = round_tf32(S/N)
// one float4 per thread over [BB, NN, DD]
// ---------------------------------------------------------------------------
__global__ void __launch_bounds__(256) addsn_kernel(float* __restrict__ Y)
{
    const size_t idx = (size_t)blockIdx.x * 256 + threadIdx.x;
    const size_t per_b = (size_t)NN * (DD / 4);
    const int b = (int)(idx / per_b);
    const size_t r = idx % per_b;
    const int i = (int)(r / (DD / 4));
    const int d4 = (int)(r % (DD / 4)) * 4;
    const int len = g_len[b];
    const float invN = 1.0f / (float)NN;

    float4 sn = *(const float4*)&g_S[b * DD + d4];
    sn.x *= invN; sn.y *= invN; sn.z *= invN; sn.w *= invN;

    float4 y;
    if (i < len) {
        y = *(float4*)&Y[idx * 4];
        y.x += sn.x; y.y += sn.y; y.z += sn.z; y.w += sn.w;
    } else {
        y = sn;
    }
    y.x = __uint_as_float(f2tf(y.x));
    y.y = __uint_as_float(f2tf(y.y));
    y.z = __uint_as_float(f2tf(y.z));
    y.w = __uint_as_float(f2tf(y.w));
    *(float4*)&Y[idx * 4] = y;
}

// ---------------------------------------------------------------------------
// out[b, i>=len, :] = yS[b,:]   (after out-proj GEMM)
// ---------------------------------------------------------------------------
__global__ void __launch_bounds__(256) bcast_out_kernel(float* __restrict__ out)
{
    const size_t idx = (size_t)blockIdx.x * 256 + threadIdx.x;
    const size_t per_b = (size_t)NN * (DD / 4);
    const int b = (int)(idx / per_b);
    const size_t r = idx % per_b;
    const int i = (int)(r / (DD / 4));
    const int d4 = (int)(r % (DD / 4)) * 4;
    if (i < g_len[b]) return;
    float4 v = *(const float4*)&g_YS[b * DD + d4];
    *(float4*)&out[idx * 4] = v;
}

// ---------------------------------------------------------------------------
// tf32 tiled GEMM, CTA tile 128x128x16, 4-stage cp.async pipeline.
// 8 warps (2 M x 4 N), warp tile 64x32, mma.m16n8k8.tf32.
//
// skip_mode: 0 none
//            1 skip CTA if its M-tile rows are all masked (projections / outproj)
//            2 skip CTA if M-tile or N-tile fully masked (logits)
//            3 (A^T V) skip CTA if m0>=len; else truncate K to ceil(len/16)*16
//              with A rows k>=len ZERO-FILLED (cp.async src-size 0) -- exact.
//              The uniform tail (j>=len) is added later as S/N in fp32.
// ---------------------------------------------------------------------------
#define BM 128
#define BN 128
#define BK 16
#define LDK 20
#define LDT 136
#define SSZ 2560
#define NSTAGE 4
#define SMEM_BYTES (NSTAGE * SSZ * 2 * 4)

__device__ __forceinline__ void cpasync16(uint32_t dst, const float* src)
{
    asm volatile("cp.async.cg.shared.global [%0], [%1], 16;" :: "r"(dst), "l"(src));
}

__device__ __forceinline__ void cpasync16z(uint32_t dst, const float* src, bool pred)
{
    int sz = pred ? 16 : 0;
    asm volatile("cp.async.cg.shared.global [%0], [%1], 16, %2;"
                 :: "r"(dst), "l"(src), "r"(sz));
}

template <bool A_KM, bool B_KN, bool CVT_A, bool ROUND_OUT>
__global__ void __launch_bounds__(256, 2)
gemm_tf32(const float* __restrict__ A, const float* __restrict__ B,
          float* __restrict__ C,
          int lda, int ldb, int ldc, int K,
          long long sA, long long sB, long long sC, float alpha,
          int skip_mode)
{
    extern __shared__ __align__(16) float sm[];
    float* As = sm;
    float* Bs = sm + NSTAGE * SSZ;

    const int m0 = blockIdx.y * BM;
    const int n0 = blockIdx.x * BN;

    int k_hi = K;
    int a_klim = 0x7fffffff;
    if (skip_mode == 1) {
        if ((m0 % NN) >= g_len[m0 / NN]) return;
    } else if (skip_mode == 2) {
        const int len = g_len[blockIdx.z];
        if (m0 >= len || n0 >= len) return;
    } else if (skip_mode == 3) {
        const int len = g_len[blockIdx.z];
        if (m0 >= len) return;
        k_hi = (len + BK - 1) & ~(BK - 1);   // <= K since len <= NN
        a_klim = len;
    }

    const int tid = threadIdx.x;
    const float* Ab = A + (long long)blockIdx.z * sA;
    const float* Bb = B + (long long)blockIdx.z * sB;
    float* Cb = C + (long long)blockIdx.z * sC;

    const int warp = tid >> 5, lane = tid & 31;
    const int wm = warp >> 2, wn = warp & 3;
    const int gr = lane >> 2, gc = lane & 3;

    const uint32_t sA0 = (uint32_t)__cvta_generic_to_shared(As);
    const uint32_t sB0 = (uint32_t)__cvta_generic_to_shared(Bs);

    float acc[4][4][4];
    #pragma unroll
    for (int mf = 0; mf < 4; mf++)
        #pragma unroll
        for (int nf = 0; nf < 4; nf++)
            #pragma unroll
            for (int r = 0; r < 4; r++) acc[mf][nf][r] = 0.0f;

    auto stage = [&](int buf, int k0) {
        #pragma unroll
        for (int it = 0; it < 2; ++it) {
            int c = tid + it * 256;
            if (!A_KM) {
                int row = c >> 2, koff = (c & 3) * 4;
                cpasync16(sA0 + (uint32_t)(buf * SSZ + row * LDK + koff) * 4u,
                          Ab + (long long)(m0 + row) * lda + k0 + koff);
            } else {
                int row = c >> 5, toff = (c & 31) * 4;
                cpasync16z(sA0 + (uint32_t)(buf * SSZ + row * LDT + toff) * 4u,
                           Ab + (long long)(k0 + row) * lda + m0 + toff,
                           (k0 + row) < a_klim);
            }
        }
        #pragma unroll
        for (int it = 0; it < 2; ++it) {
            int c = tid + it * 256;
            if (!B_KN) {
                int row = c >> 2, koff = (c & 3) * 4;
                cpasync16(sB0 + (uint32_t)(buf * SSZ + row * LDK + koff) * 4u,
                          Bb + (long long)(n0 + row) * ldb + k0 + koff);
            } else {
                int row = c >> 5, toff = (c & 31) * 4;
                cpasync16(sB0 + (uint32_t)(buf * SSZ + row * LDT + toff) * 4u,
                          Bb + (long long)(k0 + row) * ldb + n0 + toff);
            }
        }
        asm volatile("cp.async.commit_group;");
    };

    auto lda_frag = [&](const float* p) -> uint32_t {
        return CVT_A ? f2tf(*p) : __float_as_uint(*p);
    };

    auto compute = [&](int buf) {
        const float* sa = &As[buf * SSZ];
        const float* sb = &Bs[buf * SSZ];
        #pragma unroll
        for (int kk = 0; kk < BK; kk += 8) {
            uint32_t a[4][4];
            #pragma unroll
            for (int mf = 0; mf < 4; mf++) {
                int mr = wm * 64 + mf * 16 + gr;
                if (!A_KM) {
                    a[mf][0] = lda_frag(&sa[(mr    ) * LDK + kk + gc    ]);
                    a[mf][1] = lda_frag(&sa[(mr + 8) * LDK + kk + gc    ]);
                    a[mf][2] = lda_frag(&sa[(mr    ) * LDK + kk + gc + 4]);
                    a[mf][3] = lda_frag(&sa[(mr + 8) * LDK + kk + gc + 4]);
                } else {
                    a[mf][0] = lda_frag(&sa[(kk + gc    ) * LDT + mr    ]);
                    a[mf][1] = lda_frag(&sa[(kk + gc    ) * LDT + mr + 8]);
                    a[mf][2] = lda_frag(&sa[(kk + gc + 4) * LDT + mr    ]);
                    a[mf][3] = lda_frag(&sa[(kk + gc + 4) * LDT + mr + 8]);
                }
            }
            uint32_t b[4][2];
            #pragma unroll
            for (int nf = 0; nf < 4; nf++) {
                int nc = wn * 32 + nf * 8 + gr;
                if (!B_KN) {
                    b[nf][0] = __float_as_uint(sb[nc * LDK + kk + gc    ]);
                    b[nf][1] = __float_as_uint(sb[nc * LDK + kk + gc + 4]);
                } else {
                    b[nf][0] = __float_as_uint(sb[(kk + gc    ) * LDT + nc]);
                    b[nf][1] = __float_as_uint(sb[(kk + gc + 4) * LDT + nc]);
                }
            }
            #pragma unroll
            for (int mf = 0; mf < 4; mf++)
                #pragma unroll
                for (int nf = 0; nf < 4; nf++) {
                    asm volatile(
                        "mma.sync.aligned.m16n8k8.row.col.f32.tf32.tf32.f32 "
                        "{%0,%1,%2,%3},{%4,%5,%6,%7},{%8,%9},{%0,%1,%2,%3};"
                        : "+f"(acc[mf][nf][0]), "+f"(acc[mf][nf][1]),
                          "+f"(acc[mf][nf][2]), "+f"(acc[mf][nf][3])
                        : "r"(a[mf][0]), "r"(a[mf][1]), "r"(a[mf][2]), "r"(a[mf][3]),
                          "r"(b[nf][0]), "r"(b[nf][1]));
                }
        }
    };

    // ---- prologue: fill 3 of 4 stages (k_hi >= 1024 in all modes) ----
    stage(0, 0);
    stage(1, BK);
    stage(2, 2 * BK);
    asm volatile("cp.async.wait_group 2;");
    __syncthreads();

    int buf = 0;
    for (int k0 = 0; k0 < k_hi; k0 += BK) {
        if (k0 + 3 * BK < k_hi) stage((buf + 3) & 3, k0 + 3 * BK);
        else                    asm volatile("cp.async.commit_group;");  // uniform FIFO
        compute(buf);
        asm volatile("cp.async.wait_group 2;");
        __syncthreads();
        buf = (buf + 1) & 3;
    }

    // ---- epilogue ----
    #pragma unroll
    for (int mf = 0; mf < 4; mf++) {
        #pragma unroll
        for (int nf = 0; nf < 4; nf++) {
            int row = m0 + wm * 64 + mf * 16 + gr;
            int col = n0 + wn * 32 + nf * 8 + gc * 2;
            float o0 = acc[mf][nf][0] * alpha, o1 = acc[mf][nf][1] * alpha;
            float o2 = acc[mf][nf][2] * alpha, o3 = acc[mf][nf][3] * alpha;
            if (ROUND_OUT) {
                o0 = __uint_as_float(f2tf(o0));
                o1 = __uint_as_float(f2tf(o1));
                o2 = __uint_as_float(f2tf(o2));
                o3 = __uint_as_float(f2tf(o3));
            }
            *(float2*)&Cb[(long long)row * ldc + col]       = make_float2(o0, o1);
            *(float2*)&Cb[(long long)(row + 8) * ldc + col] = make_float2(o2, o3);
        }
    }
}

// ---------------------------------------------------------------------------
// Masked softmax over the last axis, in place on att [B, N, N].
// Overwrites EVERY element; masked entries become exact 0 / uniform rows.
// ---------------------------------------------------------------------------
__global__ void __launch_bounds__(256) softmax_kernel(float* __restrict__ att)
{
    const int b = blockIdx.y, i = blockIdx.x, tid = threadIdx.x;
    const int len = g_len[b];
    float* row = att + ((size_t)b * NN + i) * NN;

    if (i >= len) {
        const float u = 1.0f / (float)NN;
        for (int j = tid; j < NN; j += 256) row[j] = u;
        return;
    }

    float v[8];
    float mx = -3.4e38f;
    #pragma unroll
    for (int s = 0; s < 8; s++) {
        int j = tid + s * 256;
        v[s] = (j < len) ? row[j] : -3.4e38f;
        mx = fmaxf(mx, v[s]);
    }
    #pragma unroll
    for (int o = 16; o > 0; o >>= 1) mx = fmaxf(mx, __shfl_xor_sync(0xffffffffu, mx, o));
    __shared__ float sred[8];
    if ((tid & 31) == 0) sred[tid >> 5] = mx;
    __syncthreads();
    float M = sred[0];
    #pragma unroll
    for (int w = 1; w < 8; w++) M = fmaxf(M, sred[w]);

    float sum = 0.0f;
    #pragma unroll
    for (int s = 0; s < 8; s++) {
        int j = tid + s * 256;
        v[s] = (j < len) ? expf(v[s] - M) : 0.0f;
        sum += v[s];
    }
    #pragma unroll
    for (int o = 16; o > 0; o >>= 1) sum += __shfl_xor_sync(0xffffffffu, sum, o);
    __syncthreads();
    if ((tid & 31) == 0) sred[tid >> 5] = sum;
    __syncthreads();
    float S = 0.0f;
    #pragma unroll
    for (int w = 0; w < 8; w++) S += sred[w];
    const float inv = 1.0f / S;

    #pragma unroll
    for (int s = 0; s < 8; s++) {
        int j = tid + s * 256;
        row[j] = v[s] * inv;
    }
}

// ---------------------------------------------------------------------------
// Launch. Output layout: y [B,N,D] followed by att_weights [B,N,N].
// ---------------------------------------------------------------------------
extern "C" void kernel_launch(void* const* d_in, const int* in_sizes, int n_in,
                              void* d_out, int out_size)
{
    const float* x  = (const float*)d_in[0];
    const unsigned char* mask = (const unsigned char*)d_in[1];
    const float* Wq = (const float*)d_in[2];
    const float* Wk = (const float*)d_in[3];
    const float* Wv = (const float*)d_in[4];
    const float* Wo = (const float*)d_in[5];

    float* y_out = (float*)d_out;
    float* att   = (float*)d_out + (size_t)BB * NN * DD;

    void *pQ, *pK, *pV, *pY, *pX, *pWq, *pWk, *pWv, *pWo;
    cudaGetSymbolAddress(&pQ, g_Q);
    cudaGetSymbolAddress(&pK, g_K);
    cudaGetSymbolAddress(&pV, g_V);
    cudaGetSymbolAddress(&pY, g_Y);
    cudaGetSymbolAddress(&pX, g_X);
    cudaGetSymbolAddress(&pWq, g_Wq);
    cudaGetSymbolAddress(&pWk, g_Wk);
    cudaGetSymbolAddress(&pWv, g_Wv);
    cudaGetSymbolAddress(&pWo, g_Wo);
    float* Q = (float*)pQ;  float* Km = (float*)pK;
    float* V = (float*)pV;  float* Y  = (float*)pY;
    float* Xt = (float*)pX;
    float* Wqt = (float*)pWq; float* Wkt = (float*)pWk;
    float* Wvt = (float*)pWv; float* Wot = (float*)pWo;

    cudaFuncSetAttribute((const void*)gemm_tf32<false, false, false, true>,
                         cudaFuncAttributeMaxDynamicSharedMemorySize, SMEM_BYTES);
    cudaFuncSetAttribute((const void*)gemm_tf32<false, false, false, false>,
                         cudaFuncAttributeMaxDynamicSharedMemorySize, SMEM_BYTES);
    cudaFuncSetAttribute((const void*)gemm_tf32<true, true, true, false>,
                         cudaFuncAttributeMaxDynamicSharedMemorySize, SMEM_BYTES);

    const dim3 blk(256);

    // 0) mask lengths, pre-rounding, masked-row sums
    mask_len_kernel<<<BB, 256>>>(mask);
    cvt_tf32_kernel<<<(BB * NN * DD / 4 + 255) / 256, 256>>>(x,  Xt,  BB * NN * DD / 4);
    cvt_tf32_kernel<<<(DD * DD / 4 + 255) / 256, 256>>>(Wq, Wqt, DD * DD / 4);
    cvt_tf32_kernel<<<(DD * DD / 4 + 255) / 256, 256>>>(Wk, Wkt, DD * DD / 4);
    cvt_tf32_kernel<<<(DD * DD / 4 + 255) / 256, 256>>>(Wv, Wvt, DD * DD / 4);
    cvt_tf32_kernel<<<(DD * DD / 4 + 255) / 256, 256>>>(Wo, Wot, DD * DD / 4);
    {
        dim3 g1(DD / 256, BB);
        sumx_kernel<<<g1, 256>>>(x);                    // sx = sum_{j>=len} x[j]
        dim3 g2(DD / 8, BB);
        matvecS_kernel<<<g2, 256>>>(Wv);                // S = sx @ Wv^T (fp32)
        matvecYS_kernel<<<g2, 256>>>(Wot);              // yS = round(S/N) @ Wot^T
    }

    // 1) QKV projections -- ALL skip masked row-tiles now (V's masked rows
    //    feed only S, which is computed from x directly)
    {
        dim3 grid(DD / BN, (BB * NN) / BM, 1);
        gemm_tf32<false, false, false, true><<<grid, blk, SMEM_BYTES>>>(
            Xt, Wqt, Q,  DD, DD, DD, DD, 0, 0, 0, 0.06f, 1);
        gemm_tf32<false, false, false, true><<<grid, blk, SMEM_BYTES>>>(
            Xt, Wkt, Km, DD, DD, DD, DD, 0, 0, 0, 1.0f, 1);
        gemm_tf32<false, false, false, true><<<grid, blk, SMEM_BYTES>>>(
            Xt, Wvt, V,  DD, DD, DD, DD, 0, 0, 0, 1.0f, 1);
    }

    // 2) logits = Q @ K^T per batch (skip fully-masked tiles); att stays fp32
    {
        dim3 grid(NN / BN, NN / BM, BB);
        gemm_tf32<false, false, false, false><<<grid, blk, SMEM_BYTES>>>(
            Q, Km, att, DD, DD, NN, DD,
            (long long)NN * DD, (long long)NN * DD, (long long)NN * NN, 1.0f, 2);
    }

    // 3) masked softmax (in place; finalizes att_weights output)
    {
        dim3 grid(NN, BB);
        softmax_kernel<<<grid, 256>>>(att);
    }

    // 4) Y_partial = A^T V restricted to j<len (K truncated, zero-filled tail);
    //    masked-row tiles skipped. Raw fp32 out (rounding happens in addsn).
    {
        dim3 grid(DD / BN, NN / BM, BB);
        gemm_tf32<true, true, true, false><<<grid, blk, SMEM_BYTES>>>(
            att, V, Y, NN, DD, DD, NN,
            (long long)NN * NN, (long long)NN * DD, (long long)NN * DD, 1.0f, 3);
    }

    // 4b) Y = round_tf32(Y_partial + S/N)  (i<len);  Y = round_tf32(S/N)  (i>=len)
    addsn_kernel<<<BB * NN * DD / 4 / 256, 256>>>(Y);

    // 5) output projection: out = Y @ Wo^T; fully-masked row tiles skipped
    {
        dim3 grid(DD / BN, (BB * NN) / BM, 1);
        gemm_tf32<false, false, false, false><<<grid, blk, SMEM_BYTES>>>(
            Y, Wot, y_out, DD, DD, DD, DD, 0, 0, 0, 1.0f, 1);
    }

    // 5b) out rows i>=len = yS (covers skipped tiles; overwrites boundary-tile
    //     masked rows too -- deterministic, runs last)
    bcast_out_kernel<<<BB * NN * DD / 4 / 256, 256>>>(y_out);
}

// round 8
// speedup vs baseline: 1.0592x; 1.0019x over previous
#include <cuda_runtime.h>
#include <stdint.h>
#include <math.h>

// Problem constants
#define BB 8
#define NN 2048
#define DD 1024

// Scratch (static device globals -- runtime allocation is forbidden).
// Zero-initialized at load; skipped (masked) rows stay 0 forever.
__device__ float g_Q[BB * NN * DD];
__device__ float g_K[BB * NN * DD];
__device__ float g_V[BB * NN * DD];
__device__ float g_Y[BB * NN * DD];
__device__ float g_X[BB * NN * DD];    // tf32-rounded copy of x
__device__ float g_Wq[DD * DD];        // tf32-rounded weights
__device__ float g_Wk[DD * DD];
__device__ float g_Wv[DD * DD];
__device__ float g_Wo[DD * DD];
__device__ float g_SX[BB * DD];        // sum of masked x rows
__device__ float g_S [BB * DD];        // S = sum_{j>=len} V[j]  (fp32, via x)
__device__ float g_YS[BB * DD];        // yS = round(S/N) @ Wo^T
__device__ int   g_len[BB];

__device__ __forceinline__ uint32_t f2tf(float f)
{
    uint32_t r;
    asm("cvt.rna.tf32.f32 %0, %1;" : "=r"(r) : "f"(f));
    return r;
}

// ---------------------------------------------------------------------------
// Mask length probe (prefix mask, element [0,1] is always true)
// ---------------------------------------------------------------------------
__global__ void mask_len_kernel(const unsigned char* __restrict__ m)
{
    const int b = blockIdx.x, tid = threadIdx.x;
    int mode;
    if (m[1] != 0) {
        mode = 0;
    } else {
        uint32_t w0 = *(const uint32_t*)m;
        mode = (w0 == 0x3f800000u) ? 2 : 1;
    }
    int cnt = 0;
    for (int i = tid; i < NN; i += 256) {
        size_t idx = (size_t)b * NN + i;
        bool t;
        if (mode == 0)      t = m[idx] != 0;
        else if (mode == 1) t = ((const int*)m)[idx] != 0;
        else                t = ((const float*)m)[idx] != 0.0f;
        cnt += t ? 1 : 0;
    }
    #pragma unroll
    for (int o = 16; o > 0; o >>= 1) cnt += __shfl_xor_sync(0xffffffffu, cnt, o);
    __shared__ int sc[8];
    if ((tid & 31) == 0) sc[tid >> 5] = cnt;
    __syncthreads();
    if (tid == 0) {
        int t = 0;
        #pragma unroll
        for (int w = 0; w < 8; w++) t += sc[w];
        g_len[b] = t;
    }
}

// ---------------------------------------------------------------------------
// Elementwise tf32 rounding
// ---------------------------------------------------------------------------
__global__ void __launch_bounds__(256) cvt_tf32_kernel(
    const float* __restrict__ in, float* __restrict__ out, int n4)
{
    int i = blockIdx.x * 256 + threadIdx.x;
    if (i < n4) {
        float4 v = ((const float4*)in)[i];
        v.x = __uint_as_float(f2tf(v.x));
        v.y = __uint_as_float(f2tf(v.y));
        v.z = __uint_as_float(f2tf(v.z));
        v.w = __uint_as_float(f2tf(v.w));
        ((float4*)out)[i] = v;
    }
}

// ---------------------------------------------------------------------------
// sx[b,d] = sum_{j>=len} x[b,j,d]   (fp32, raw x)   grid(DD/256, BB)
// ---------------------------------------------------------------------------
__global__ void __launch_bounds__(256) sumx_kernel(const float* __restrict__ x)
{
    const int b = blockIdx.y;
    const int d = blockIdx.x * 256 + threadIdx.x;
    const int len = g_len[b];
    float s = 0.0f;
    for (int j = len; j < NN; ++j)
        s += x[((size_t)b * NN + j) * DD + d];
    g_SX[b * DD + d] = s;
}

// ---------------------------------------------------------------------------
// S[b,e] = sum_d sx[b,d] * Wv[e,d]  (fp32, raw Wv)   grid(DD/8, BB), blk 256
// ---------------------------------------------------------------------------
__global__ void __launch_bounds__(256) matvecS_kernel(const float* __restrict__ Wv)
{
    const int b = blockIdx.y;
    const int wid = threadIdx.x >> 5, lane = threadIdx.x & 31;
    const int e = blockIdx.x * 8 + wid;
    const float* sx = &g_SX[b * DD];
    const float* w = &Wv[(size_t)e * DD];
    float acc = 0.0f;
    for (int d = lane; d < DD; d += 32) acc += sx[d] * w[d];
    #pragma unroll
    for (int o = 16; o > 0; o >>= 1) acc += __shfl_xor_sync(0xffffffffu, acc, o);
    if (lane == 0) g_S[b * DD + e] = acc;
}

// ---------------------------------------------------------------------------
// yS[b,e] = sum_d round_tf32(S[b,d]/N) * Wot[e,d]   grid(DD/8, BB), blk 256
// (Wot = tf32-rounded Wo, matching the GEMM operand)
// ---------------------------------------------------------------------------
__global__ void __launch_bounds__(256) matvecYS_kernel(const float* __restrict__ Wot)
{
    const int b = blockIdx.y;
    const int wid = threadIdx.x >> 5, lane = threadIdx.x & 31;
    const int e = blockIdx.x * 8 + wid;
    const float invN = 1.0f / (float)NN;
    const float* S = &g_S[b * DD];
    const float* w = &Wot[(size_t)e * DD];
    float acc = 0.0f;
    for (int d = lane; d < DD; d += 32)
        acc += __uint_as_float(f2tf(S[d] * invN)) * w[d];
    #pragma unroll
    for (int o = 16; o > 0; o >>= 1) acc += __shfl_xor_sync(0xffffffffu, acc, o);
    if (lane == 0) g_YS[b * DD + e] = acc;
}

// ---------------------------------------------------------------------------
// Y finalize: i<len: Y = round_tf32(Yraw + S/N); i>=len: Y = round_tf32(S/N)
// one float4 per thread over [BB, NN, DD]
// ---------------------------------------------------------------------------
__global__ void __launch_bounds__(256) addsn_kernel(float* __restrict__ Y)
{
    const size_t idx = (size_t)blockIdx.x * 256 + threadIdx.x;
    const size_t per_b = (size_t)NN * (DD / 4);
    const int b = (int)(idx / per_b);
    const size_t r = idx % per_b;
    const int i = (int)(r / (DD / 4));
    const int d4 = (int)(r % (DD / 4)) * 4;
    const int len = g_len[b];
    const float invN = 1.0f / (float)NN;

    float4 sn = *(const float4*)&g_S[b * DD + d4];
    sn.x *= invN; sn.y *= invN; sn.z *= invN; sn.w *= invN;

    float4 y;
    if (i < len) {
        y = *(float4*)&Y[idx * 4];
        y.x += sn.x; y.y += sn.y; y.z += sn.z; y.w += sn.w;
    } else {
        y = sn;
    }
    y.x = __uint_as_float(f2tf(y.x));
    y.y = __uint_as_float(f2tf(y.y));
    y.z = __uint_as_float(f2tf(y.z));
    y.w = __uint_as_float(f2tf(y.w));
    *(float4*)&Y[idx * 4] = y;
}

// ---------------------------------------------------------------------------
// out[b, i>=len, :] = yS[b,:]   (after out-proj GEMM)
// ---------------------------------------------------------------------------
__global__ void __launch_bounds__(256) bcast_out_kernel(float* __restrict__ out)
{
    const size_t idx = (size_t)blockIdx.x * 256 + threadIdx.x;
    const size_t per_b = (size_t)NN * (DD / 4);
    const int b = (int)(idx / per_b);
    const size_t r = idx % per_b;
    const int i = (int)(r / (DD / 4));
    const int d4 = (int)(r % (DD / 4)) * 4;
    if (i < g_len[b]) return;
    float4 v = *(const float4*)&g_YS[b * DD + d4];
    *(float4*)&out[idx * 4] = v;
}

// ---------------------------------------------------------------------------
// tf32 tiled GEMM, CTA tile 128x128x16, 4-stage cp.async pipeline.
// 8 warps (2 M x 4 N), warp tile 64x32, mma.m16n8k8.tf32.
//
// skip_mode: 0 none
//            1 skip CTA if its M-tile rows are all masked (projections / outproj)
//            2 skip CTA if M-tile or N-tile fully masked (logits)
//            3 (A^T V) skip CTA if m0>=len; else truncate K to ceil(len/16)*16
//              with A rows k>=len ZERO-FILLED (cp.async src-size 0) -- exact.
//              The uniform tail (j>=len) is added later as S/N in fp32.
// ---------------------------------------------------------------------------
#define BM 128
#define BN 128
#define BK 16
#define LDK 20
#define LDT 136
#define SSZ 2560
#define NSTAGE 4
#define SMEM_BYTES (NSTAGE * SSZ * 2 * 4)

__device__ __forceinline__ void cpasync16(uint32_t dst, const float* src)
{
    asm volatile("cp.async.cg.shared.global [%0], [%1], 16;" :: "r"(dst), "l"(src));
}

__device__ __forceinline__ void cpasync16z(uint32_t dst, const float* src, bool pred)
{
    int sz = pred ? 16 : 0;
    asm volatile("cp.async.cg.shared.global [%0], [%1], 16, %2;"
                 :: "r"(dst), "l"(src), "r"(sz));
}

template <bool A_KM, bool B_KN, bool CVT_A, bool ROUND_OUT>
__global__ void __launch_bounds__(256, 2)
gemm_tf32(const float* __restrict__ A, const float* __restrict__ B,
          float* __restrict__ C,
          int lda, int ldb, int ldc, int K,
          long long sA, long long sB, long long sC, float alpha,
          int skip_mode)
{
    extern __shared__ __align__(16) float sm[];
    float* As = sm;
    float* Bs = sm + NSTAGE * SSZ;

    const int m0 = blockIdx.y * BM;
    const int n0 = blockIdx.x * BN;

    int k_hi = K;
    int a_klim = 0x7fffffff;
    if (skip_mode == 1) {
        if ((m0 % NN) >= g_len[m0 / NN]) return;
    } else if (skip_mode == 2) {
        const int len = g_len[blockIdx.z];
        if (m0 >= len || n0 >= len) return;
    } else if (skip_mode == 3) {
        const int len = g_len[blockIdx.z];
        if (m0 >= len) return;
        k_hi = (len + BK - 1) & ~(BK - 1);   // <= K since len <= NN
        a_klim = len;
    }

    const int tid = threadIdx.x;
    const float* Ab = A + (long long)blockIdx.z * sA;
    const float* Bb = B + (long long)blockIdx.z * sB;
    float* Cb = C + (long long)blockIdx.z * sC;

    const int warp = tid >> 5, lane = tid & 31;
    const int wm = warp >> 2, wn = warp & 3;
    const int gr = lane >> 2, gc = lane & 3;

    const uint32_t sA0 = (uint32_t)__cvta_generic_to_shared(As);
    const uint32_t sB0 = (uint32_t)__cvta_generic_to_shared(Bs);

    float acc[4][4][4];
    #pragma unroll
    for (int mf = 0; mf < 4; mf++)
        #pragma unroll
        for (int nf = 0; nf < 4; nf++)
            #pragma unroll
            for (int r = 0; r < 4; r++) acc[mf][nf][r] = 0.0f;

    auto stage = [&](int buf, int k0) {
        #pragma unroll
        for (int it = 0; it < 2; ++it) {
            int c = tid + it * 256;
            if (!A_KM) {
                int row = c >> 2, koff = (c & 3) * 4;
                cpasync16(sA0 + (uint32_t)(buf * SSZ + row * LDK + koff) * 4u,
                          Ab + (long long)(m0 + row) * lda + k0 + koff);
            } else {
                int row = c >> 5, toff = (c & 31) * 4;
                cpasync16z(sA0 + (uint32_t)(buf * SSZ + row * LDT + toff) * 4u,
                           Ab + (long long)(k0 + row) * lda + m0 + toff,
                           (k0 + row) < a_klim);
            }
        }
        #pragma unroll
        for (int it = 0; it < 2; ++it) {
            int c = tid + it * 256;
            if (!B_KN) {
                int row = c >> 2, koff = (c & 3) * 4;
                cpasync16(sB0 + (uint32_t)(buf * SSZ + row * LDK + koff) * 4u,
                          Bb + (long long)(n0 + row) * ldb + k0 + koff);
            } else {
                int row = c >> 5, toff = (c & 31) * 4;
                cpasync16(sB0 + (uint32_t)(buf * SSZ + row * LDT + toff) * 4u,
                          Bb + (long long)(k0 + row) * ldb + n0 + toff);
            }
        }
        asm volatile("cp.async.commit_group;");
    };

    auto lda_frag = [&](const float* p) -> uint32_t {
        return CVT_A ? f2tf(*p) : __float_as_uint(*p);
    };

    auto compute = [&](int buf) {
        const float* sa = &As[buf * SSZ];
        const float* sb = &Bs[buf * SSZ];
        #pragma unroll
        for (int kk = 0; kk < BK; kk += 8) {
            uint32_t a[4][4];
            #pragma unroll
            for (int mf = 0; mf < 4; mf++) {
                int mr = wm * 64 + mf * 16 + gr;
                if (!A_KM) {
                    a[mf][0] = lda_frag(&sa[(mr    ) * LDK + kk + gc    ]);
                    a[mf][1] = lda_frag(&sa[(mr + 8) * LDK + kk + gc    ]);
                    a[mf][2] = lda_frag(&sa[(mr    ) * LDK + kk + gc + 4]);
                    a[mf][3] = lda_frag(&sa[(mr + 8) * LDK + kk + gc + 4]);
                } else {
                    a[mf][0] = lda_frag(&sa[(kk + gc    ) * LDT + mr    ]);
                    a[mf][1] = lda_frag(&sa[(kk + gc    ) * LDT + mr + 8]);
                    a[mf][2] = lda_frag(&sa[(kk + gc + 4) * LDT + mr    ]);
                    a[mf][3] = lda_frag(&sa[(kk + gc + 4) * LDT + mr + 8]);
                }
            }
            uint32_t b[4][2];
            #pragma unroll
            for (int nf = 0; nf < 4; nf++) {
                int nc = wn * 32 + nf * 8 + gr;
                if (!B_KN) {
                    b[nf][0] = __float_as_uint(sb[nc * LDK + kk + gc    ]);
                    b[nf][1] = __float_as_uint(sb[nc * LDK + kk + gc + 4]);
                } else {
                    b[nf][0] = __float_as_uint(sb[(kk + gc    ) * LDT + nc]);
                    b[nf][1] = __float_as_uint(sb[(kk + gc + 4) * LDT + nc]);
                }
            }
            #pragma unroll
            for (int mf = 0; mf < 4; mf++)
                #pragma unroll
                for (int nf = 0; nf < 4; nf++) {
                    asm volatile(
                        "mma.sync.aligned.m16n8k8.row.col.f32.tf32.tf32.f32 "
                        "{%0,%1,%2,%3},{%4,%5,%6,%7},{%8,%9},{%0,%1,%2,%3};"
                        : "+f"(acc[mf][nf][0]), "+f"(acc[mf][nf][1]),
                          "+f"(acc[mf][nf][2]), "+f"(acc[mf][nf][3])
                        : "r"(a[mf][0]), "r"(a[mf][1]), "r"(a[mf][2]), "r"(a[mf][3]),
                          "r"(b[nf][0]), "r"(b[nf][1]));
                }
        }
    };

    // ---- prologue: fill 3 of 4 stages (k_hi >= 1024 in all modes) ----
    stage(0, 0);
    stage(1, BK);
    stage(2, 2 * BK);
    asm volatile("cp.async.wait_group 2;");
    __syncthreads();

    int buf = 0;
    for (int k0 = 0; k0 < k_hi; k0 += BK) {
        if (k0 + 3 * BK < k_hi) stage((buf + 3) & 3, k0 + 3 * BK);
        else                    asm volatile("cp.async.commit_group;");  // uniform FIFO
        compute(buf);
        asm volatile("cp.async.wait_group 2;");
        __syncthreads();
        buf = (buf + 1) & 3;
    }

    // ---- epilogue ----
    #pragma unroll
    for (int mf = 0; mf < 4; mf++) {
        #pragma unroll
        for (int nf = 0; nf < 4; nf++) {
            int row = m0 + wm * 64 + mf * 16 + gr;
            int col = n0 + wn * 32 + nf * 8 + gc * 2;
            float o0 = acc[mf][nf][0] * alpha, o1 = acc[mf][nf][1] * alpha;
            float o2 = acc[mf][nf][2] * alpha, o3 = acc[mf][nf][3] * alpha;
            if (ROUND_OUT) {
                o0 = __uint_as_float(f2tf(o0));
                o1 = __uint_as_float(f2tf(o1));
                o2 = __uint_as_float(f2tf(o2));
                o3 = __uint_as_float(f2tf(o3));
            }
            *(float2*)&Cb[(long long)row * ldc + col]       = make_float2(o0, o1);
            *(float2*)&Cb[(long long)(row + 8) * ldc + col] = make_float2(o2, o3);
        }
    }
}

// ---------------------------------------------------------------------------
// Masked softmax over the last axis, in place on att [B, N, N].
// Overwrites EVERY element; masked entries become exact 0 / uniform rows.
// ---------------------------------------------------------------------------
__global__ void __launch_bounds__(256) softmax_kernel(float* __restrict__ att)
{
    const int b = blockIdx.y, i = blockIdx.x, tid = threadIdx.x;
    const int len = g_len[b];
    float* row = att + ((size_t)b * NN + i) * NN;

    if (i >= len) {
        const float u = 1.0f / (float)NN;
        for (int j = tid; j < NN; j += 256) row[j] = u;
        return;
    }

    float v[8];
    float mx = -3.4e38f;
    #pragma unroll
    for (int s = 0; s < 8; s++) {
        int j = tid + s * 256;
        v[s] = (j < len) ? row[j] : -3.4e38f;
        mx = fmaxf(mx, v[s]);
    }
    #pragma unroll
    for (int o = 16; o > 0; o >>= 1) mx = fmaxf(mx, __shfl_xor_sync(0xffffffffu, mx, o));
    __shared__ float sred[8];
    if ((tid & 31) == 0) sred[tid >> 5] = mx;
    __syncthreads();
    float M = sred[0];
    #pragma unroll
    for (int w = 1; w < 8; w++) M = fmaxf(M, sred[w]);

    float sum = 0.0f;
    #pragma unroll
    for (int s = 0; s < 8; s++) {
        int j = tid + s * 256;
        v[s] = (j < len) ? expf(v[s] - M) : 0.0f;
        sum += v[s];
    }
    #pragma unroll
    for (int o = 16; o > 0; o >>= 1) sum += __shfl_xor_sync(0xffffffffu, sum, o);
    __syncthreads();
    if ((tid & 31) == 0) sred[tid >> 5] = sum;
    __syncthreads();
    float S = 0.0f;
    #pragma unroll
    for (int w = 0; w < 8; w++) S += sred[w];
    const float inv = 1.0f / S;

    #pragma unroll
    for (int s = 0; s < 8; s++) {
        int j = tid + s * 256;
        row[j] = v[s] * inv;
    }
}

// ---------------------------------------------------------------------------
// Launch. Output layout: y [B,N,D] followed by att_weights [B,N,N].
// ---------------------------------------------------------------------------
extern "C" void kernel_launch(void* const* d_in, const int* in_sizes, int n_in,
                              void* d_out, int out_size)
{
    const float* x  = (const float*)d_in[0];
    const unsigned char* mask = (const unsigned char*)d_in[1];
    const float* Wq = (const float*)d_in[2];
    const float* Wk = (const float*)d_in[3];
    const float* Wv = (const float*)d_in[4];
    const float* Wo = (const float*)d_in[5];

    float* y_out = (float*)d_out;
    float* att   = (float*)d_out + (size_t)BB * NN * DD;

    void *pQ, *pK, *pV, *pY, *pX, *pWq, *pWk, *pWv, *pWo;
    cudaGetSymbolAddress(&pQ, g_Q);
    cudaGetSymbolAddress(&pK, g_K);
    cudaGetSymbolAddress(&pV, g_V);
    cudaGetSymbolAddress(&pY, g_Y);
    cudaGetSymbolAddress(&pX, g_X);
    cudaGetSymbolAddress(&pWq, g_Wq);
    cudaGetSymbolAddress(&pWk, g_Wk);
    cudaGetSymbolAddress(&pWv, g_Wv);
    cudaGetSymbolAddress(&pWo, g_Wo);
    float* Q = (float*)pQ;  float* Km = (float*)pK;
    float* V = (float*)pV;  float* Y  = (float*)pY;
    float* Xt = (float*)pX;
    float* Wqt = (float*)pWq; float* Wkt = (float*)pWk;
    float* Wvt = (float*)pWv; float* Wot = (float*)pWo;

    cudaFuncSetAttribute((const void*)gemm_tf32<false, false, false, true>,
                         cudaFuncAttributeMaxDynamicSharedMemorySize, SMEM_BYTES);
    cudaFuncSetAttribute((const void*)gemm_tf32<false, false, false, false>,
                         cudaFuncAttributeMaxDynamicSharedMemorySize, SMEM_BYTES);
    cudaFuncSetAttribute((const void*)gemm_tf32<true, true, true, false>,
                         cudaFuncAttributeMaxDynamicSharedMemorySize, SMEM_BYTES);

    const dim3 blk(256);

    // 0) mask lengths, pre-rounding, masked-row sums
    mask_len_kernel<<<BB, 256>>>(mask);
    cvt_tf32_kernel<<<(BB * NN * DD / 4 + 255) / 256, 256>>>(x,  Xt,  BB * NN * DD / 4);
    cvt_tf32_kernel<<<(DD * DD / 4 + 255) / 256, 256>>>(Wq, Wqt, DD * DD / 4);
    cvt_tf32_kernel<<<(DD * DD / 4 + 255) / 256, 256>>>(Wk, Wkt, DD * DD / 4);
    cvt_tf32_kernel<<<(DD * DD / 4 + 255) / 256, 256>>>(Wv, Wvt, DD * DD / 4);
    cvt_tf32_kernel<<<(DD * DD / 4 + 255) / 256, 256>>>(Wo, Wot, DD * DD / 4);
    {
        dim3 g1(DD / 256, BB);
        sumx_kernel<<<g1, 256>>>(x);                    // sx = sum_{j>=len} x[j]
        dim3 g2(DD / 8, BB);
        matvecS_kernel<<<g2, 256>>>(Wv);                // S = sx @ Wv^T (fp32)
        matvecYS_kernel<<<g2, 256>>>(Wot);              // yS = round(S/N) @ Wot^T
    }

    // 1) QKV projections -- ALL skip masked row-tiles now (V's masked rows
    //    feed only S, which is computed from x directly)
    {
        dim3 grid(DD / BN, (BB * NN) / BM, 1);
        gemm_tf32<false, false, false, true><<<grid, blk, SMEM_BYTES>>>(
            Xt, Wqt, Q,  DD, DD, DD, DD, 0, 0, 0, 0.06f, 1);
        gemm_tf32<false, false, false, true><<<grid, blk, SMEM_BYTES>>>(
            Xt, Wkt, Km, DD, DD, DD, DD, 0, 0, 0, 1.0f, 1);
        gemm_tf32<false, false, false, true><<<grid, blk, SMEM_BYTES>>>(
            Xt, Wvt, V,  DD, DD, DD, DD, 0, 0, 0, 1.0f, 1);
    }

    // 2) logits = Q @ K^T per batch (skip fully-masked tiles); att stays fp32
    {
        dim3 grid(NN / BN, NN / BM, BB);
        gemm_tf32<false, false, false, false><<<grid, blk, SMEM_BYTES>>>(
            Q, Km, att, DD, DD, NN, DD,
            (long long)NN * DD, (long long)NN * DD, (long long)NN * NN, 1.0f, 2);
    }

    // 3) masked softmax (in place; finalizes att_weights output)
    {
        dim3 grid(NN, BB);
        softmax_kernel<<<grid, 256>>>(att);
    }

    // 4) Y_partial = A^T V restricted to j<len (K truncated, zero-filled tail);
    //    masked-row tiles skipped. Raw fp32 out (rounding happens in addsn).
    {
        dim3 grid(DD / BN, NN / BM, BB);
        gemm_tf32<true, true, true, false><<<grid, blk, SMEM_BYTES>>>(
            att, V, Y, NN, DD, DD, NN,
            (long long)NN * NN, (long long)NN * DD, (long long)NN * DD, 1.0f, 3);
    }

    // 4b) Y = round_tf32(Y_partial + S/N)  (i<len);  Y = round_tf32(S/N)  (i>=len)
    addsn_kernel<<<BB * NN * DD / 4 / 256, 256>>>(Y);

    // 5) output projection: out = Y @ Wo^T; fully-masked row tiles skipped
    {
        dim3 grid(DD / BN, (BB * NN) / BM, 1);
        gemm_tf32<false, false, false, false><<<grid, blk, SMEM_BYTES>>>(
            Y, Wot, y_out, DD, DD, DD, DD, 0, 0, 0, 1.0f, 1);
    }

    // 5b) out rows i>=len = yS (covers skipped tiles; overwrites boundary-tile
    //     masked rows too -- deterministic, runs last)
    bcast_out_kernel<<<BB * NN * DD / 4 / 256, 256>>>(y_out);
}